// round 10
// baseline (speedup 1.0000x reference)
#include <cuda_runtime.h>
#include <cuda_fp16.h>

#define BB 64
#define CC 32
#define NN 1152
#define DI 8
#define DC 16
#define PP 512            // C*DC
#define CH 16             // route n-chunks per b
#define NPW 9             // n per warp = NN/(CH*8)

// Scratch (allocation-free: __device__ globals)
__device__ __half g_hat[(size_t)BB*NN*PP];   // [B,N,C,DC] fp16, 75.5 MB
__device__ float  g_s[3][BB*PP];             // s0,s1,s2 accumulators

// ---------------- hat: inputs_hat[b,n,c,i] = sum_j W[c,n,i,j]*x[b,n,j] ----------------
__global__ __launch_bounds__(256) void hat_kernel(const float* __restrict__ x,
                                                  const float* __restrict__ W) {
    int n = blockIdx.x;
    int t = threadIdx.x;
    if (n < 3) {  // fold s-accumulator zeroing in (ordered by launch boundary)
        for (int e = t; e < BB*PP; e += 256) g_s[n][e] = 0.0f;
    }
    __shared__ float4 Ws4[1024];   // 16 KB
    __shared__ float4 xs4[128];    // 2 KB

    const float4* W4 = reinterpret_cast<const float4*>(W);
    const float4* x4 = reinterpret_cast<const float4*>(x);
#pragma unroll
    for (int f = t; f < 1024; f += 256) {
        int c = f >> 5, rem = f & 31;
        Ws4[f] = W4[(size_t)c*NN*32 + (size_t)n*32 + rem];
    }
    if (t < 128) {
        int b = t >> 1, hf = t & 1;
        xs4[t] = x4[(size_t)b*NN*2 + (size_t)n*2 + hf];
    }
    __syncthreads();

    float4 wa0 = Ws4[4*t+0], wb0 = Ws4[4*t+1];
    float4 wa1 = Ws4[4*t+2], wb1 = Ws4[4*t+3];
    __half2* hp = reinterpret_cast<__half2*>(g_hat);

#pragma unroll 4
    for (int b = 0; b < BB; b++) {
        float4 xa = xs4[2*b], xb = xs4[2*b+1];
        float a0 = fmaf(wa0.x, xa.x, fmaf(wa0.y, xa.y, fmaf(wa0.z, xa.z, wa0.w*xa.w)));
        a0 = fmaf(wb0.x, xb.x, fmaf(wb0.y, xb.y, fmaf(wb0.z, xb.z, fmaf(wb0.w, xb.w, a0))));
        float a1 = fmaf(wa1.x, xa.x, fmaf(wa1.y, xa.y, fmaf(wa1.z, xa.z, wa1.w*xa.w)));
        a1 = fmaf(wb1.x, xb.x, fmaf(wb1.y, xb.y, fmaf(wb1.z, xb.z, fmaf(wb1.w, xb.w, a1))));
        hp[((size_t)(b*NN + n))*256 + t] = __floats2half2_rn(a0, a1);
    }
}

// ---------------- helpers ----------------
__device__ __forceinline__ void unpack8(const uint4& u, float* h) {
    const __half2* p = reinterpret_cast<const __half2*>(&u);
#pragma unroll
    for (int k = 0; k < 4; k++) {
        float2 f = __half22float2(p[k]);
        h[2*k] = f.x; h[2*k+1] = f.y;
    }
}

__device__ __forceinline__ void squash16_add(const float* __restrict__ s, int off,
                                             float* dv, bool add) {
    const float4* p = reinterpret_cast<const float4*>(s + off);
    float v[16];
    float4 q0 = p[0], q1 = p[1], q2 = p[2], q3 = p[3];
    v[0]=q0.x; v[1]=q0.y; v[2]=q0.z; v[3]=q0.w;
    v[4]=q1.x; v[5]=q1.y; v[6]=q1.z; v[7]=q1.w;
    v[8]=q2.x; v[9]=q2.y; v[10]=q2.z; v[11]=q2.w;
    v[12]=q3.x; v[13]=q3.y; v[14]=q3.z; v[15]=q3.w;
    float sq = 0.f;
#pragma unroll
    for (int i = 0; i < 16; i++) sq = fmaf(v[i], v[i], sq);
    float sc = sq / (1.0f + sq) * rsqrtf(sq + 1e-7f);
#pragma unroll
    for (int i = 0; i < 16; i++) dv[i] = add ? fmaf(sc, v[i], dv[i]) : sc * v[i];
}

// load a group of 3 consecutive n's (6 uint4) for this lane
__device__ __forceinline__ void load_grp3(const uint4* __restrict__ hp, size_t base,
                                          uint4* u) {
#pragma unroll
    for (int k = 0; k < 3; k++) {
        u[2*k]   = hp[base + (size_t)k*64];
        u[2*k+1] = hp[base + (size_t)k*64 + 1];
    }
}

// ---------------- fused routing pass (warp-per-n, pipelined loads, short softmax) ----
// MODE 0: uniform 1/32 weights. MODE 1: dv=squash(sp0)[+squash(sp1)]; softmax over c.
template<int MODE>
__global__ __launch_bounds__(256, 8) void route_kernel(const float* __restrict__ sp0,
                                                       const float* __restrict__ sp1,
                                                       float* __restrict__ sout) {
    int b = blockIdx.y;
    int w = threadIdx.x >> 5;
    int c = threadIdx.x & 31;

    float dv[16];
#pragma unroll
    for (int i = 0; i < 16; i++) dv[i] = 0.f;
    if (MODE == 1) {
        squash16_add(sp0, b*PP + c*DC, dv, false);
        if (sp1) squash16_add(sp1, b*PP + c*DC, dv, true);
    }

    float acc[16];
#pragma unroll
    for (int i = 0; i < 16; i++) acc[i] = 0.f;

    const uint4* hp = reinterpret_cast<const uint4*>(g_hat);
    int n0 = blockIdx.x * (8*NPW) + w * NPW;
    size_t base = ((size_t)(b*NN + n0)) * 64 + c*2;   // uint4 units; +64 per n

    // double-buffered groups of 3 n's: 12 uint4 in flight at steady state
    uint4 ua[6], ub[6];
    load_grp3(hp, base,           ua);
    load_grp3(hp, base + 3*64,    ub);

#pragma unroll
    for (int g = 0; g < 3; g++) {
        uint4* cur = (g & 1) ? ub : ua;
        // prefetch group g+2 into the buffer just being consumed... (g<1 only: g+2=2 -> ua? )
        if (g == 0) { /* next-next into ua after it is consumed below */ }
#pragma unroll
        for (int k = 0; k < 3; k++) {
            float h[16];
            unpack8(cur[2*k], h);
            unpack8(cur[2*k+1], h + 8);
            float wgt;
            if (MODE == 0) {
                wgt = 1.0f / CC;
            } else {
                float d = 0.f;
#pragma unroll
                for (int i = 0; i < 16; i++) d = fmaf(dv[i], h[i], d);
                // shift-invariant softmax without max-pass (logits bounded ~|7|)
                float e = __expf(d);
                float es = e;
#pragma unroll
                for (int o = 16; o > 0; o >>= 1) es += __shfl_xor_sync(0xffffffffu, es, o);
                wgt = __fdividef(e, es);
            }
#pragma unroll
            for (int i = 0; i < 16; i++) acc[i] = fmaf(wgt, h[i], acc[i]);
        }
        if (g == 0) load_grp3(hp, base + 6*64, ua);   // refill for g=2
    }

    // block-level reduce (8 warps) then one atomicAdd set
    __shared__ float red[8*PP];   // 16 KB
    float4* rp = reinterpret_cast<float4*>(&red[w*PP + c*DC]);
    rp[0] = make_float4(acc[0], acc[1], acc[2], acc[3]);
    rp[1] = make_float4(acc[4], acc[5], acc[6], acc[7]);
    rp[2] = make_float4(acc[8], acc[9], acc[10], acc[11]);
    rp[3] = make_float4(acc[12], acc[13], acc[14], acc[15]);
    __syncthreads();

    int e0 = threadIdx.x * 2;
    float r0 = 0.f, r1 = 0.f;
#pragma unroll
    for (int ww = 0; ww < 8; ww++) {
        float2 v = *reinterpret_cast<float2*>(&red[ww*PP + e0]);
        r0 += v.x; r1 += v.y;
    }
    atomicAdd(&sout[b*PP + e0],     r0);
    atomicAdd(&sout[b*PP + e0 + 1], r1);
}

// ---------------- final squash -> output [B,C,DC] ----------------
__global__ __launch_bounds__(256) void squash_out_kernel(const float* __restrict__ s,
                                                         float* __restrict__ out) {
    int b = blockIdx.x * 8 + (threadIdx.x >> 5);
    int c = threadIdx.x & 31;
    float dv[16];
    squash16_add(s, b*PP + c*DC, dv, false);
    float4* op = reinterpret_cast<float4*>(out + b*PP + c*DC);
    op[0] = make_float4(dv[0], dv[1], dv[2], dv[3]);
    op[1] = make_float4(dv[4], dv[5], dv[6], dv[7]);
    op[2] = make_float4(dv[8], dv[9], dv[10], dv[11]);
    op[3] = make_float4(dv[12], dv[13], dv[14], dv[15]);
}

extern "C" void kernel_launch(void* const* d_in, const int* in_sizes, int n_in,
                              void* d_out, int out_size) {
    const float* x = (const float*)d_in[0];
    const float* W = (const float*)d_in[1];
    if (in_sizes[0] != BB*NN*DI) { const float* tmp = x; x = W; W = tmp; }
    float* out = (float*)d_out;

    float* ss;
    cudaGetSymbolAddress((void**)&ss, g_s);

    hat_kernel<<<NN, 256>>>(x, W);               // also zeroes s0,s1,s2

    dim3 rg(CH, BB);
    route_kernel<0><<<rg, 256>>>(nullptr, nullptr, ss);
    route_kernel<1><<<rg, 256>>>(ss, nullptr, ss + BB*PP);
    route_kernel<1><<<rg, 256>>>(ss, ss + BB*PP, ss + 2*BB*PP);
    squash_out_kernel<<<BB/8, 256>>>(ss + 2*BB*PP, out);
}

// round 15
// speedup vs baseline: 1.2270x; 1.2270x over previous
#include <cuda_runtime.h>
#include <cuda_fp16.h>

#define BB 64
#define CC 32
#define NN 1152
#define DI 8
#define DC 16
#define PP 512            // C*DC
#define CH 16             // route n-chunks per b
#define NPW 9             // n per warp = NN/(CH*8)

// Scratch (allocation-free: __device__ globals)
__device__ __half g_hat[(size_t)BB*NN*PP];   // [B,N,C,DC] fp16, 75.5 MB
__device__ float  g_s[3][BB*PP];             // s0,s1,s2 accumulators

// ---------------- hat: inputs_hat[b,n,c,i] = sum_j W[c,n,i,j]*x[b,n,j] ----------------
__global__ __launch_bounds__(256) void hat_kernel(const float* __restrict__ x,
                                                  const float* __restrict__ W) {
    int n = blockIdx.x;
    int t = threadIdx.x;
    if (n < 3) {  // fold s-accumulator zeroing in (ordered by launch boundary)
        for (int e = t; e < BB*PP; e += 256) g_s[n][e] = 0.0f;
    }
    __shared__ float4 Ws4[1024];   // 16 KB
    __shared__ float4 xs4[128];    // 2 KB

    const float4* W4 = reinterpret_cast<const float4*>(W);
    const float4* x4 = reinterpret_cast<const float4*>(x);
#pragma unroll
    for (int f = t; f < 1024; f += 256) {
        int c = f >> 5, rem = f & 31;
        Ws4[f] = W4[(size_t)c*NN*32 + (size_t)n*32 + rem];
    }
    if (t < 128) {
        int b = t >> 1, hf = t & 1;
        xs4[t] = x4[(size_t)b*NN*2 + (size_t)n*2 + hf];
    }
    __syncthreads();

    float4 wa0 = Ws4[4*t+0], wb0 = Ws4[4*t+1];
    float4 wa1 = Ws4[4*t+2], wb1 = Ws4[4*t+3];
    __half2* hp = reinterpret_cast<__half2*>(g_hat);

#pragma unroll 4
    for (int b = 0; b < BB; b++) {
        float4 xa = xs4[2*b], xb = xs4[2*b+1];
        float a0 = fmaf(wa0.x, xa.x, fmaf(wa0.y, xa.y, fmaf(wa0.z, xa.z, wa0.w*xa.w)));
        a0 = fmaf(wb0.x, xb.x, fmaf(wb0.y, xb.y, fmaf(wb0.z, xb.z, fmaf(wb0.w, xb.w, a0))));
        float a1 = fmaf(wa1.x, xa.x, fmaf(wa1.y, xa.y, fmaf(wa1.z, xa.z, wa1.w*xa.w)));
        a1 = fmaf(wb1.x, xb.x, fmaf(wb1.y, xb.y, fmaf(wb1.z, xb.z, fmaf(wb1.w, xb.w, a1))));
        hp[((size_t)(b*NN + n))*256 + t] = __floats2half2_rn(a0, a1);
    }
}

// ---------------- helpers ----------------
__device__ __forceinline__ void unpack8(const uint4& u, float* h) {
    const __half2* p = reinterpret_cast<const __half2*>(&u);
#pragma unroll
    for (int k = 0; k < 4; k++) {
        float2 f = __half22float2(p[k]);
        h[2*k] = f.x; h[2*k+1] = f.y;
    }
}

__device__ __forceinline__ void squash16_add(const float* __restrict__ s, int off,
                                             float* dv, bool add) {
    const float4* p = reinterpret_cast<const float4*>(s + off);
    float v[16];
    float4 q0 = p[0], q1 = p[1], q2 = p[2], q3 = p[3];
    v[0]=q0.x; v[1]=q0.y; v[2]=q0.z; v[3]=q0.w;
    v[4]=q1.x; v[5]=q1.y; v[6]=q1.z; v[7]=q1.w;
    v[8]=q2.x; v[9]=q2.y; v[10]=q2.z; v[11]=q2.w;
    v[12]=q3.x; v[13]=q3.y; v[14]=q3.z; v[15]=q3.w;
    float sq = 0.f;
#pragma unroll
    for (int i = 0; i < 16; i++) sq = fmaf(v[i], v[i], sq);
    float sc = sq / (1.0f + sq) * rsqrtf(sq + 1e-7f);
#pragma unroll
    for (int i = 0; i < 16; i++) dv[i] = add ? fmaf(sc, v[i], dv[i]) : sc * v[i];
}

// ---------------- fused routing pass ----------------------------------------
// Warp-per-n; ALL 9 n's (18 uint4/lane) loaded up front (MLP=18), then
// 9 dots -> 9 interleaved butterfly sums -> 9 accumulations. No buffer reuse.
// MODE 0: uniform 1/32 weights. MODE 1: dv=squash(sp0)[+squash(sp1)]; softmax over c.
template<int MODE>
__global__ __launch_bounds__(256) void route_kernel(const float* __restrict__ sp0,
                                                    const float* __restrict__ sp1,
                                                    float* __restrict__ sout) {
    int b = blockIdx.y;
    int w = threadIdx.x >> 5;
    int c = threadIdx.x & 31;

    float dv[16];
#pragma unroll
    for (int i = 0; i < 16; i++) dv[i] = 0.f;
    if (MODE == 1) {
        squash16_add(sp0, b*PP + c*DC, dv, false);
        if (sp1) squash16_add(sp1, b*PP + c*DC, dv, true);
    }

    const uint4* hp = reinterpret_cast<const uint4*>(g_hat);
    int n0 = blockIdx.x * (8*NPW) + w * NPW;
    size_t base = ((size_t)(b*NN + n0)) * 64 + c*2;   // uint4 units; +64 per n

    // batch-load the warp's entire slice: 18 independent LDG.128 in flight
    uint4 u[2*NPW];
#pragma unroll
    for (int k = 0; k < NPW; k++) {
        u[2*k]   = hp[base + (size_t)k*64];
        u[2*k+1] = hp[base + (size_t)k*64 + 1];
    }

    float wgt[NPW];
    if (MODE == 0) {
#pragma unroll
        for (int k = 0; k < NPW; k++) wgt[k] = 1.0f / CC;
    } else {
        // phase 1: 9 independent dots + exps (transient unpack)
        float e[NPW], es[NPW];
#pragma unroll
        for (int k = 0; k < NPW; k++) {
            float h[16];
            unpack8(u[2*k], h);
            unpack8(u[2*k+1], h + 8);
            float d = 0.f;
#pragma unroll
            for (int i = 0; i < 16; i++) d = fmaf(dv[i], h[i], d);
            e[k] = __expf(d);              // shift-invariant softmax, logits bounded
            es[k] = e[k];
        }
        // phase 2: 9 butterfly sums interleaved — chains overlap in the scheduler
#pragma unroll
        for (int o = 16; o > 0; o >>= 1) {
#pragma unroll
            for (int k = 0; k < NPW; k++)
                es[k] += __shfl_xor_sync(0xffffffffu, es[k], o);
        }
#pragma unroll
        for (int k = 0; k < NPW; k++) wgt[k] = __fdividef(e[k], es[k]);
    }

    // phase 3: accumulate (re-unpack from live registers)
    float acc[16];
#pragma unroll
    for (int i = 0; i < 16; i++) acc[i] = 0.f;
#pragma unroll
    for (int k = 0; k < NPW; k++) {
        float h[16];
        unpack8(u[2*k], h);
        unpack8(u[2*k+1], h + 8);
#pragma unroll
        for (int i = 0; i < 16; i++) acc[i] = fmaf(wgt[k], h[i], acc[i]);
    }

    // block-level reduce (8 warps) then one atomicAdd set
    __shared__ float red[8*PP];   // 16 KB
    float4* rp = reinterpret_cast<float4*>(&red[w*PP + c*DC]);
    rp[0] = make_float4(acc[0], acc[1], acc[2], acc[3]);
    rp[1] = make_float4(acc[4], acc[5], acc[6], acc[7]);
    rp[2] = make_float4(acc[8], acc[9], acc[10], acc[11]);
    rp[3] = make_float4(acc[12], acc[13], acc[14], acc[15]);
    __syncthreads();

    int e0 = threadIdx.x * 2;
    float r0 = 0.f, r1 = 0.f;
#pragma unroll
    for (int ww = 0; ww < 8; ww++) {
        float2 v = *reinterpret_cast<float2*>(&red[ww*PP + e0]);
        r0 += v.x; r1 += v.y;
    }
    atomicAdd(&sout[b*PP + e0],     r0);
    atomicAdd(&sout[b*PP + e0 + 1], r1);
}

// ---------------- final squash -> output [B,C,DC] ----------------
__global__ __launch_bounds__(256) void squash_out_kernel(const float* __restrict__ s,
                                                         float* __restrict__ out) {
    int b = blockIdx.x * 8 + (threadIdx.x >> 5);
    int c = threadIdx.x & 31;
    float dv[16];
    squash16_add(s, b*PP + c*DC, dv, false);
    float4* op = reinterpret_cast<float4*>(out + b*PP + c*DC);
    op[0] = make_float4(dv[0], dv[1], dv[2], dv[3]);
    op[1] = make_float4(dv[4], dv[5], dv[6], dv[7]);
    op[2] = make_float4(dv[8], dv[9], dv[10], dv[11]);
    op[3] = make_float4(dv[12], dv[13], dv[14], dv[15]);
}

extern "C" void kernel_launch(void* const* d_in, const int* in_sizes, int n_in,
                              void* d_out, int out_size) {
    const float* x = (const float*)d_in[0];
    const float* W = (const float*)d_in[1];
    if (in_sizes[0] != BB*NN*DI) { const float* tmp = x; x = W; W = tmp; }
    float* out = (float*)d_out;

    float* ss;
    cudaGetSymbolAddress((void**)&ss, g_s);

    hat_kernel<<<NN, 256>>>(x, W);               // also zeroes s0,s1,s2

    dim3 rg(CH, BB);
    route_kernel<0><<<rg, 256>>>(nullptr, nullptr, ss);
    route_kernel<1><<<rg, 256>>>(ss, nullptr, ss + BB*PP);
    route_kernel<1><<<rg, 256>>>(ss, ss + BB*PP, ss + 2*BB*PP);
    squash_out_kernel<<<BB/8, 256>>>(ss + 2*BB*PP, out);
}

// round 16
// speedup vs baseline: 1.3578x; 1.1066x over previous
#include <cuda_runtime.h>
#include <cuda_fp16.h>

#define BB 64
#define CC 32
#define NN 1152
#define DI 8
#define DC 16
#define PP 512            // C*DC
#define CH 16             // route n-chunks per b (72 n's per block)
#define NGRP 9            // groups of 8 n per block
#define NST 3             // cp.async pipeline stages

// Scratch (allocation-free: __device__ globals)
__device__ __half g_hat[(size_t)BB*NN*PP];   // [B,N,C,DC] fp16, 75.5 MB
__device__ float  g_s[3][BB*PP];             // s0,s1,s2 accumulators

// ---------------- hat: inputs_hat[b,n,c,i] = sum_j W[c,n,i,j]*x[b,n,j] ----------------
__global__ __launch_bounds__(256) void hat_kernel(const float* __restrict__ x,
                                                  const float* __restrict__ W) {
    int n = blockIdx.x;
    int t = threadIdx.x;
    if (n < 3) {  // fold s-accumulator zeroing in (ordered by launch boundary)
        for (int e = t; e < BB*PP; e += 256) g_s[n][e] = 0.0f;
    }
    __shared__ float4 Ws4[1024];   // 16 KB
    __shared__ float4 xs4[128];    // 2 KB

    const float4* W4 = reinterpret_cast<const float4*>(W);
    const float4* x4 = reinterpret_cast<const float4*>(x);
#pragma unroll
    for (int f = t; f < 1024; f += 256) {
        int c = f >> 5, rem = f & 31;
        Ws4[f] = W4[(size_t)c*NN*32 + (size_t)n*32 + rem];
    }
    if (t < 128) {
        int b = t >> 1, hf = t & 1;
        xs4[t] = x4[(size_t)b*NN*2 + (size_t)n*2 + hf];
    }
    __syncthreads();

    float4 wa0 = Ws4[4*t+0], wb0 = Ws4[4*t+1];
    float4 wa1 = Ws4[4*t+2], wb1 = Ws4[4*t+3];
    __half2* hp = reinterpret_cast<__half2*>(g_hat);

#pragma unroll 4
    for (int b = 0; b < BB; b++) {
        float4 xa = xs4[2*b], xb = xs4[2*b+1];
        float a0 = fmaf(wa0.x, xa.x, fmaf(wa0.y, xa.y, fmaf(wa0.z, xa.z, wa0.w*xa.w)));
        a0 = fmaf(wb0.x, xb.x, fmaf(wb0.y, xb.y, fmaf(wb0.z, xb.z, fmaf(wb0.w, xb.w, a0))));
        float a1 = fmaf(wa1.x, xa.x, fmaf(wa1.y, xa.y, fmaf(wa1.z, xa.z, wa1.w*xa.w)));
        a1 = fmaf(wb1.x, xb.x, fmaf(wb1.y, xb.y, fmaf(wb1.z, xb.z, fmaf(wb1.w, xb.w, a1))));
        hp[((size_t)(b*NN + n))*256 + t] = __floats2half2_rn(a0, a1);
    }
}

// ---------------- helpers ----------------
__device__ __forceinline__ void unpack8(const uint4& u, float* h) {
    const __half2* p = reinterpret_cast<const __half2*>(&u);
#pragma unroll
    for (int k = 0; k < 4; k++) {
        float2 f = __half22float2(p[k]);
        h[2*k] = f.x; h[2*k+1] = f.y;
    }
}

__device__ __forceinline__ void squash16_add(const float* __restrict__ s, int off,
                                             float* dv, bool add) {
    const float4* p = reinterpret_cast<const float4*>(s + off);
    float v[16];
    float4 q0 = p[0], q1 = p[1], q2 = p[2], q3 = p[3];
    v[0]=q0.x; v[1]=q0.y; v[2]=q0.z; v[3]=q0.w;
    v[4]=q1.x; v[5]=q1.y; v[6]=q1.z; v[7]=q1.w;
    v[8]=q2.x; v[9]=q2.y; v[10]=q2.z; v[11]=q2.w;
    v[12]=q3.x; v[13]=q3.y; v[14]=q3.z; v[15]=q3.w;
    float sq = 0.f;
#pragma unroll
    for (int i = 0; i < 16; i++) sq = fmaf(v[i], v[i], sq);
    float sc = sq / (1.0f + sq) * rsqrtf(sq + 1e-7f);
#pragma unroll
    for (int i = 0; i < 16; i++) dv[i] = add ? fmaf(sc, v[i], dv[i]) : sc * v[i];
}

// ---------------- iter-0: s0[b,p] = (1/32) * sum_n hat[b,n,p] --------------------
// Pure coalesced streaming reduction; grid (BB, 8) over n-segments of 144.
__global__ __launch_bounds__(256) void mean_kernel(float* __restrict__ s0) {
    int b = blockIdx.x, seg = blockIdx.y;
    int t = threadIdx.x;
    int o  = t & 63;          // uint4 chunk within a row (8 halves)
    int ng = t >> 6;          // 4 n-lanes
    const uint4* hb = reinterpret_cast<const uint4*>(g_hat)
                    + ((size_t)(b*NN + seg*144 + ng))*64 + o;
    float acc[8];
#pragma unroll
    for (int i = 0; i < 8; i++) acc[i] = 0.f;
#pragma unroll 4
    for (int k = 0; k < 36; k++) {
        uint4 u = hb[(size_t)k*4*64];
        float h[8];
        unpack8(u, h);
#pragma unroll
        for (int i = 0; i < 8; i++) acc[i] += h[i];
    }
#pragma unroll
    for (int i = 0; i < 8; i++)
        atomicAdd(&s0[b*PP + o*8 + i], acc[i] * (1.0f/CC));
}

// ---------------- cp.async primitives ----------------
__device__ __forceinline__ void cp16(unsigned smem_dst, const void* gsrc) {
    asm volatile("cp.async.cg.shared.global [%0], [%1], 16;\n"
                 :: "r"(smem_dst), "l"(gsrc));
}
__device__ __forceinline__ void cp_commit() {
    asm volatile("cp.async.commit_group;\n" ::: "memory");
}
template<int N> __device__ __forceinline__ void cp_wait() {
    asm volatile("cp.async.wait_group %0;\n" :: "n"(N) : "memory");
}

// ---------------- fused routing pass (cp.async smem staging) ------------------
// Block = (nchunk, b): 72 n's in 9 groups of 8; 3-stage pipeline; warp-per-n consume.
// dv = squash(sp0) [+ squash(sp1)]; logits = dv.hat; softmax over c; accumulate.
// Stage layout per row: chunk o (16B, halves 8o..8o+8) stored at slot (o&1)*32 + o/2,
// so lane c reads slots c and 32+c (16B lane stride -> conflict-free LDS.128).
__global__ __launch_bounds__(256) void route_kernel(const float* __restrict__ sp0,
                                                    const float* __restrict__ sp1,
                                                    float* __restrict__ sout) {
    __shared__ uint4 pool[NST*512];   // 24 KB: 3 stages x (8 rows x 64 slots); reused as reduce buf
    int b = blockIdx.y;
    int t = threadIdx.x;
    int w = t >> 5;
    int c = t & 31;

    float dv[16];
    squash16_add(sp0, b*PP + c*DC, dv, false);
    if (sp1) squash16_add(sp1, b*PP + c*DC, dv, true);

    int n0 = blockIdx.x * (8*NGRP);
    const char* gb = reinterpret_cast<const char*>(g_hat) + ((size_t)(b*NN + n0))*1024;
    unsigned sbase = (unsigned)__cvta_generic_to_shared(pool);

    // issue_group(g, st): 256 threads copy 512 x 16B chunks (2 each), permuted slots
    auto issue = [&](int g, int st) {
#pragma unroll
        for (int q = t; q < 512; q += 256) {
            int r = q >> 6, o = q & 63;
            int slot = ((o & 1) << 5) | (o >> 1);
            cp16(sbase + (unsigned)((st*512 + r*64 + slot) * 16),
                 gb + ((size_t)(g*8 + r))*1024 + o*16);
        }
        cp_commit();
    };

    issue(0, 0); issue(1, 1); issue(2, 2);

    float acc[16];
#pragma unroll
    for (int i = 0; i < 16; i++) acc[i] = 0.f;

#pragma unroll
    for (int g = 0; g < NGRP; g++) {
        int rem = (NGRP - 1) - g;
        if (rem >= 2)      cp_wait<2>();
        else if (rem == 1) cp_wait<1>();
        else               cp_wait<0>();
        __syncthreads();

        // consume: warp w handles row w of this stage
        const uint4* row = pool + (g % NST)*512 + w*64;
        uint4 ua = row[c];
        uint4 ub = row[32 + c];
        float h[16];
        unpack8(ua, h);
        unpack8(ub, h + 8);
        float d = 0.f;
#pragma unroll
        for (int i = 0; i < 16; i++) d = fmaf(dv[i], h[i], d);
        float e = __expf(d);               // shift-invariant softmax, logits bounded
        float es = e;
#pragma unroll
        for (int o = 16; o > 0; o >>= 1) es += __shfl_xor_sync(0xffffffffu, es, o);
        float wgt = __fdividef(e, es);
#pragma unroll
        for (int i = 0; i < 16; i++) acc[i] = fmaf(wgt, h[i], acc[i]);

        __syncthreads();                   // all warps done with this stage
        if (g + NST < NGRP) issue(g + NST, g % NST);
    }

    // block-level reduce (8 warps) in the stage memory, then one atomicAdd set
    float* red = reinterpret_cast<float*>(pool);   // needs 16 KB <= 24 KB
    float4* rp = reinterpret_cast<float4*>(&red[w*PP + c*DC]);
    rp[0] = make_float4(acc[0], acc[1], acc[2], acc[3]);
    rp[1] = make_float4(acc[4], acc[5], acc[6], acc[7]);
    rp[2] = make_float4(acc[8], acc[9], acc[10], acc[11]);
    rp[3] = make_float4(acc[12], acc[13], acc[14], acc[15]);
    __syncthreads();

    int e0 = t * 2;
    float r0 = 0.f, r1 = 0.f;
#pragma unroll
    for (int ww = 0; ww < 8; ww++) {
        float2 v = *reinterpret_cast<float2*>(&red[ww*PP + e0]);
        r0 += v.x; r1 += v.y;
    }
    atomicAdd(&sout[b*PP + e0],     r0);
    atomicAdd(&sout[b*PP + e0 + 1], r1);
}

// ---------------- final squash -> output [B,C,DC] ----------------
__global__ __launch_bounds__(256) void squash_out_kernel(const float* __restrict__ s,
                                                         float* __restrict__ out) {
    int b = blockIdx.x * 8 + (threadIdx.x >> 5);
    int c = threadIdx.x & 31;
    float dv[16];
    squash16_add(s, b*PP + c*DC, dv, false);
    float4* op = reinterpret_cast<float4*>(out + b*PP + c*DC);
    op[0] = make_float4(dv[0], dv[1], dv[2], dv[3]);
    op[1] = make_float4(dv[4], dv[5], dv[6], dv[7]);
    op[2] = make_float4(dv[8], dv[9], dv[10], dv[11]);
    op[3] = make_float4(dv[12], dv[13], dv[14], dv[15]);
}

extern "C" void kernel_launch(void* const* d_in, const int* in_sizes, int n_in,
                              void* d_out, int out_size) {
    const float* x = (const float*)d_in[0];
    const float* W = (const float*)d_in[1];
    if (in_sizes[0] != BB*NN*DI) { const float* tmp = x; x = W; W = tmp; }
    float* out = (float*)d_out;

    float* ss;
    cudaGetSymbolAddress((void**)&ss, g_s);

    hat_kernel<<<NN, 256>>>(x, W);                       // writes hat, zeroes s0..s2
    mean_kernel<<<dim3(BB, 8), 256>>>(ss);               // iter 0: s0 = mean_n(hat)

    dim3 rg(CH, BB);
    route_kernel<<<rg, 256>>>(ss, nullptr, ss + BB*PP);          // iter 1 -> s1
    route_kernel<<<rg, 256>>>(ss, ss + BB*PP, ss + 2*BB*PP);     // iter 2 -> s2
    squash_out_kernel<<<BB/8, 256>>>(ss + 2*BB*PP, out);         // out = squash(s2)
}